// round 13
// baseline (speedup 1.0000x reference)
#include <cuda_runtime.h>
#include <math.h>

#define DT 0.01f
#define TPB     256
#define CHUNK   1024                   // elements per warp
#define NCHUNK  8192                   // 8388608 / 1024
#define GRID1   512                    // k_partial: 8 warps x 2 chunks each
#define GRID3   1024                   // k_final:   8 warps x 1 chunk each
#define LSEG    8                      // elements per lane per round (k_final)
#define LPAD    9                      // staging stride (float2) per lane

// Tuples (A,P,X,V): v' = A*v + V ; x' = x + P*v + X
__device__ float4 g_chunk[NCHUNK];
__device__ float4 g_pref [NCHUNK];

__device__ __forceinline__ float4 comp(float4 f, float4 g) {
    float4 r;
    r.x = g.x * f.x;
    r.y = f.y + g.y * f.x;
    r.z = f.z + g.y * f.w + g.z;
    r.w = g.x * f.w + g.w;
    return r;
}
__device__ __forceinline__ float4 ident() { return make_float4(1.f, 0.f, 0.f, 0.f); }

__device__ __forceinline__ float4 shfl_up4(float4 v, int d, unsigned m) {
    float4 r;
    r.x = __shfl_up_sync(m, v.x, d);
    r.y = __shfl_up_sync(m, v.y, d);
    r.z = __shfl_up_sync(m, v.z, d);
    r.w = __shfl_up_sync(m, v.w, d);
    return r;
}

__device__ __forceinline__ void get_coeffs(const float* mass, const float* fric,
                                           float& alpha, float& beta, float& fb) {
    float m_safe = fabsf(mass[0]) + 0.001f;
    beta  = DT / m_safe;
    fb    = fric[0] * beta;            // = 1 - alpha, no cancellation
    alpha = 1.0f - fb;
}

// ---------------- Pass 1 (R11, proven 10.3us): warp chunk tuples, batched loads ----------------
__global__ void __launch_bounds__(TPB)
k_partial(const float* __restrict__ act,
          const float* __restrict__ mass,
          const float* __restrict__ fric) {
    int lane = threadIdx.x & 31, wid = threadIdx.x >> 5;

    float alpha, beta, fb;
    get_coeffs(mass, fric, alpha, beta, fb);
    float l2a  = log2f(alpha);
    float w0   = exp2f(l2a * (float)(CHUNK - 1 - 4 * lane));
    float step = exp2f(l2a * -128.0f);
    float ai   = 1.0f / alpha;
    float ai2  = ai * ai;
    float ai3  = ai2 * ai;

    float A = alpha;
    #pragma unroll
    for (int k = 0; k < 10; k++) A *= A;                 // alpha^1024
    float denom = fb;
    if (fabsf(denom) < 1e-12f) denom = 1e-12f;
    float P = DT * alpha * (1.0f - A) / denom;

    #pragma unroll
    for (int half = 0; half < 2; half++) {
        int chunk = blockIdx.x * 8 + wid + half * (NCHUNK / 2);
        const float4* g4 = reinterpret_cast<const float4*>(act) + (size_t)chunk * (CHUNK / 4);

        float4 d[8];
        #pragma unroll
        for (int r = 0; r < 8; r++) d[r] = g4[r * 32 + lane];

        float w = w0;
        float acc0 = 0.f, acc1 = 0.f, acc2 = 0.f, acc3 = 0.f;
        float s0 = 0.f, s1 = 0.f, s2 = 0.f, s3 = 0.f;
        #pragma unroll
        for (int r = 0; r < 8; r++) {
            acc0 = fmaf(d[r].x, w, acc0);
            acc1 = fmaf(d[r].y, w, acc1);
            acc2 = fmaf(d[r].z, w, acc2);
            acc3 = fmaf(d[r].w, w, acc3);
            s0 += d[r].x; s1 += d[r].y; s2 += d[r].z; s3 += d[r].w;
            w *= step;
        }
        float W = fmaf(ai3, acc3, fmaf(ai2, acc2, fmaf(ai, acc1, acc0)));
        float S = (s0 + s1) + (s2 + s3);
        #pragma unroll
        for (int dd = 16; dd > 0; dd >>= 1) {
            W += __shfl_down_sync(0xffffffffu, W, dd);
            S += __shfl_down_sync(0xffffffffu, S, dd);
        }
        if (lane == 0) {
            float vz = beta * W;
            float xz = DT * (beta * S - alpha * vz) / denom;
            g_chunk[chunk] = make_float4(A, P, xz, vz);
        }
    }
}

// ---------------- Pass 2 (R11, proven): scan 8192 chunk tuples -> exclusive prefixes ----------------
__global__ void __launch_bounds__(1024)
k_blockscan() {
    __shared__ float4 wt[32];
    int tid = threadIdx.x, lane = tid & 31, wid = tid >> 5;

    float4 c[8];
    #pragma unroll
    for (int i = 0; i < 8; i++) c[i] = g_chunk[tid * 8 + i];
    float4 val = c[0];
    #pragma unroll
    for (int i = 1; i < 8; i++) val = comp(val, c[i]);

    #pragma unroll
    for (int d = 1; d < 32; d <<= 1) {
        float4 up = shfl_up4(val, d, 0xffffffffu);
        if (lane >= d) val = comp(up, val);
    }
    if (lane == 31) wt[wid] = val;
    __syncthreads();
    if (wid == 0) {
        float4 cc = wt[lane];
        #pragma unroll
        for (int d = 1; d < 32; d <<= 1) {
            float4 up = shfl_up4(cc, d, 0xffffffffu);
            if (lane >= d) cc = comp(up, cc);
        }
        wt[lane] = cc;
    }
    __syncthreads();
    float4 wexcl = (wid == 0) ? ident() : wt[wid - 1];
    float4 lexcl = shfl_up4(val, 1, 0xffffffffu);
    if (lane == 0) lexcl = ident();
    float4 E = comp(wexcl, lexcl);

    #pragma unroll
    for (int i = 0; i < 8; i++) {
        g_pref[tid * 8 + i] = E;
        E = comp(E, c[i]);
    }
}

// ---------------- Pass 3: warp-owned chunk, batched loads, 4 rounds of 8-elem lanes ----------------
__global__ void __launch_bounds__(TPB)
k_final(const float* __restrict__ act,
        const float* __restrict__ initst,
        const float* __restrict__ mass,
        const float* __restrict__ fric,
        float2* __restrict__ out2) {
    __shared__ __align__(16) float2 st[8][32 * LPAD];    // 18432B total
    int lane = threadIdx.x & 31, wid = threadIdx.x >> 5;
    int chunk = blockIdx.x * 8 + wid;

    float alpha, beta, fb;
    get_coeffs(mass, fric, alpha, beta, fb);
    float denom = fb;
    if (fabsf(denom) < 1e-12f) denom = 1e-12f;
    float l2a = log2f(alpha);

    // batched loads: lane owns elements r*256 + lane*8 .. +7  (2 consecutive float4s per round)
    const float4* g4 = reinterpret_cast<const float4*>(act) + (size_t)chunk * (CHUNK / 4);
    float4 d[8];
    #pragma unroll
    for (int r = 0; r < 4; r++) {
        d[2 * r + 0] = g4[r * 64 + 2 * lane + 0];
        d[2 * r + 1] = g4[r * 64 + 2 * lane + 1];
    }

    // scan step constants: at step s the right operand spans 8*2^s elements
    float A8 = alpha * alpha; A8 *= A8; A8 *= A8;        // alpha^8
    float As[5], Ps[5];
    As[0] = A8;
    #pragma unroll
    for (int s = 1; s < 5; s++) As[s] = As[s - 1] * As[s - 1];
    #pragma unroll
    for (int s = 0; s < 5; s++) Ps[s] = DT * alpha * (1.0f - As[s]) / denom;
    float A256 = As[4] * As[4];                          // alpha^256 (round advance)
    float P256 = DT * alpha * (1.0f - A256) / denom;
    float Aex = exp2f(l2a * (float)(LSEG * lane));       // alpha^(8*lane)
    float Pex = DT * alpha * (1.0f - Aex) / denom;

    // chunk incoming state
    float x0 = initst[0];
    float v0 = initst[1];
    float4 e = g_pref[chunk];
    float vv = e.x * v0 + e.w;
    float xx = x0 + e.y * v0 + e.z;

    if (chunk == 0 && lane == 0) out2[0] = make_float2(x0, v0);

    float2* ob = out2 + 1 + (size_t)chunk * CHUNK;
    float2* sw = st[wid];

    #pragma unroll
    for (int r = 0; r < 4; r++) {
        float4 a0 = d[2 * r + 0];
        float4 a1 = d[2 * r + 1];

        // zero-state (X,V) over this lane's 8 elements
        float V = beta * a0.x;            float X = DT * V;
        V = fmaf(alpha, V, beta * a0.y);  X = fmaf(DT, V, X);
        V = fmaf(alpha, V, beta * a0.z);  X = fmaf(DT, V, X);
        V = fmaf(alpha, V, beta * a0.w);  X = fmaf(DT, V, X);
        V = fmaf(alpha, V, beta * a1.x);  X = fmaf(DT, V, X);
        V = fmaf(alpha, V, beta * a1.y);  X = fmaf(DT, V, X);
        V = fmaf(alpha, V, beta * a1.z);  X = fmaf(DT, V, X);
        V = fmaf(alpha, V, beta * a1.w);  X = fmaf(DT, V, X);

        // inclusive warp scan of (X,V): uniform analytic (A,P) per step
        #pragma unroll
        for (int s = 0; s < 5; s++) {
            int dd = 1 << s;
            float Xu = __shfl_up_sync(0xffffffffu, X, dd);
            float Vu = __shfl_up_sync(0xffffffffu, V, dd);
            if (lane >= dd) {
                X = fmaf(Ps[s], Vu, X) + Xu;
                V = fmaf(As[s], Vu, V);
            }
        }
        float Xt = __shfl_sync(0xffffffffu, X, 31);      // round total
        float Vt = __shfl_sync(0xffffffffu, V, 31);
        float Xe = __shfl_up_sync(0xffffffffu, X, 1);    // exclusive per lane
        float Ve = __shfl_up_sync(0xffffffffu, V, 1);
        if (lane == 0) { Xe = 0.f; Ve = 0.f; }

        // lane start state = exclusive tuple applied to round-start state
        float vl = fmaf(Aex, vv, Ve);
        float xl = fmaf(Pex, vv, xx) + Xe;

        // replay 8 elements, stage into padded smem
        float2* so = sw + lane * LPAD;
        vl = fmaf(alpha, vl, beta * a0.x); xl = fmaf(DT, vl, xl); so[0] = make_float2(xl, vl);
        vl = fmaf(alpha, vl, beta * a0.y); xl = fmaf(DT, vl, xl); so[1] = make_float2(xl, vl);
        vl = fmaf(alpha, vl, beta * a0.z); xl = fmaf(DT, vl, xl); so[2] = make_float2(xl, vl);
        vl = fmaf(alpha, vl, beta * a0.w); xl = fmaf(DT, vl, xl); so[3] = make_float2(xl, vl);
        vl = fmaf(alpha, vl, beta * a1.x); xl = fmaf(DT, vl, xl); so[4] = make_float2(xl, vl);
        vl = fmaf(alpha, vl, beta * a1.y); xl = fmaf(DT, vl, xl); so[5] = make_float2(xl, vl);
        vl = fmaf(alpha, vl, beta * a1.z); xl = fmaf(DT, vl, xl); so[6] = make_float2(xl, vl);
        vl = fmaf(alpha, vl, beta * a1.w); xl = fmaf(DT, vl, xl); so[7] = make_float2(xl, vl);

        // advance round-start state (xx uses old vv)
        xx = fmaf(P256, vv, xx) + Xt;
        vv = fmaf(A256, vv, Vt);

        __syncwarp();
        // coalesced store of the 256 staged float2 (2KB)
        #pragma unroll
        for (int j = 0; j < 8; j++) {
            int m = 32 * j + lane;
            ob[256 * r + m] = sw[(m >> 3) * LPAD + (m & 7)];
        }
        __syncwarp();
    }
}

extern "C" void kernel_launch(void* const* d_in, const int* in_sizes, int n_in,
                              void* d_out, int out_size) {
    const float* init = (const float*)d_in[0];
    const float* act  = (const float*)d_in[1];
    const float* mass = (const float*)d_in[2];
    const float* fric = (const float*)d_in[3];
    float2* out2 = (float2*)d_out;

    k_partial<<<GRID1, TPB>>>(act, mass, fric);
    k_blockscan<<<1, 1024>>>();
    k_final<<<GRID3, TPB>>>(act, init, mass, fric, out2);
}